// round 2
// baseline (speedup 1.0000x reference)
#include <cuda_runtime.h>

// Problem constants
#define SEQ    2048
#define BATCH  2
#define HID    2048
#define NPH    16            // heads per batch
#define HN     128           // head dim
#define MTOT   (SEQ*BATCH)   // 4096 rows
#define QKVN   (3*HID)       // 6144
#define NHEADS (BATCH*NPH)   // 32
#define ATT_SCALE (1.0f/11.313708498984761f)

// Scratch (device globals — no allocation in kernel_launch allowed)
__device__ float g_qkv[(size_t)MTOT * QKVN];             // 100 MB
__device__ float g_scores[(size_t)NHEADS * SEQ * SEQ];   // 512 MB
__device__ float g_ctx[(size_t)MTOT * HID];              // 33 MB

// ---------------------------------------------------------------------------
// Generic batched tiled GEMM.
//   NT=true :  C[m,n] = alpha * sum_k A[m,k] * B[n,k]   (both K-major)
//   NT=false:  C[m,n] = alpha * sum_k A[m,k] * B[k,n]
// Per-z (blockIdx.z) pointer offsets are linear: A+z*sAz, B+z*sBz, C+z*sCz.
// All dims are exact multiples of the tile sizes (M,N % 128 == 0, K % 8 == 0).
// BM=BN=128, BK=8, 256 threads, 8x8 per-thread accumulators.
// ---------------------------------------------------------------------------
template <bool NT>
__global__ void __launch_bounds__(256)
gemm_tile(const float* __restrict__ A, int lda, long sAz,
          const float* __restrict__ B, int ldb, long sBz,
          float*       __restrict__ C, int ldc, long sCz,
          int K, float alpha)
{
    __shared__ float As[8][128];
    __shared__ float Bs[8][128];

    const int z = blockIdx.z;
    A += (long)z * sAz;
    B += (long)z * sBz;
    C += (long)z * sCz;

    const int m0 = blockIdx.y * 128;
    const int n0 = blockIdx.x * 128;
    const int t  = threadIdx.x;
    const int tx = t & 15;       // output col group
    const int ty = t >> 4;       // output row group

    // A-tile load mapping: 128 rows x 8 cols, one float4 per thread
    const int ar = t >> 1;          // 0..127
    const int ac = (t & 1) * 4;     // 0 or 4
    // B-tile (NN) load mapping: 8 rows x 128 cols
    const int br = t >> 5;          // 0..7
    const int bc = (t & 31) * 4;    // 0..124

    float acc[8][8];
#pragma unroll
    for (int i = 0; i < 8; i++)
#pragma unroll
        for (int j = 0; j < 8; j++) acc[i][j] = 0.0f;

    for (int k0 = 0; k0 < K; k0 += 8) {
        // Load A tile (transpose into As[k][m])
        float4 av = *(const float4*)(A + (long)(m0 + ar) * lda + k0 + ac);
        As[ac + 0][ar] = av.x;
        As[ac + 1][ar] = av.y;
        As[ac + 2][ar] = av.z;
        As[ac + 3][ar] = av.w;

        if (NT) {
            // B is [N,K] row-major: same pattern as A, transpose into Bs[k][n]
            float4 bv = *(const float4*)(B + (long)(n0 + ar) * ldb + k0 + ac);
            Bs[ac + 0][ar] = bv.x;
            Bs[ac + 1][ar] = bv.y;
            Bs[ac + 2][ar] = bv.z;
            Bs[ac + 3][ar] = bv.w;
        } else {
            // B is [K,N] row-major: direct copy into Bs[k][n]
            float4 bv = *(const float4*)(B + (long)(k0 + br) * ldb + n0 + bc);
            *(float4*)&Bs[br][bc] = bv;
        }
        __syncthreads();

#pragma unroll
        for (int kk = 0; kk < 8; kk++) {
            float a[8], b[8];
#pragma unroll
            for (int i = 0; i < 8; i++) a[i] = As[kk][ty * 8 + i];
#pragma unroll
            for (int j = 0; j < 8; j++) b[j] = Bs[kk][tx * 8 + j];
#pragma unroll
            for (int i = 0; i < 8; i++)
#pragma unroll
                for (int j = 0; j < 8; j++) acc[i][j] += a[i] * b[j];
        }
        __syncthreads();
    }

#pragma unroll
    for (int i = 0; i < 8; i++) {
#pragma unroll
        for (int j = 0; j < 8; j += 4) {
            float4 v = make_float4(acc[i][j + 0] * alpha,
                                   acc[i][j + 1] * alpha,
                                   acc[i][j + 2] * alpha,
                                   acc[i][j + 3] * alpha);
            *(float4*)(C + (long)(m0 + ty * 8 + i) * ldc + n0 + tx * 8 + j) = v;
        }
    }
}

// ---------------------------------------------------------------------------
// Row softmax, in place. One 256-thread block per row of length SEQ (2048).
// ---------------------------------------------------------------------------
__global__ void __launch_bounds__(256)
softmax_rows(float* __restrict__ S)
{
    __shared__ float buf[SEQ];     // 8 KB row cache
    __shared__ float red[256];

    const long row = blockIdx.x;
    float* p = S + row * (long)SEQ;
    const int t = threadIdx.x;

    float mx = -3.402823e38f;
    for (int i = t; i < SEQ; i += 256) {
        float v = p[i];
        buf[i] = v;
        mx = fmaxf(mx, v);
    }
    red[t] = mx;
    __syncthreads();
    for (int s = 128; s > 0; s >>= 1) {
        if (t < s) red[t] = fmaxf(red[t], red[t + s]);
        __syncthreads();
    }
    mx = red[0];
    __syncthreads();

    float sum = 0.0f;
    for (int i = t; i < SEQ; i += 256) {
        float e = __expf(buf[i] - mx);
        buf[i] = e;
        sum += e;
    }
    red[t] = sum;
    __syncthreads();
    for (int s = 128; s > 0; s >>= 1) {
        if (t < s) red[t] += red[t + s];
        __syncthreads();
    }
    const float inv = 1.0f / red[0];
    for (int i = t; i < SEQ; i += 256) p[i] = buf[i] * inv;
}

// ---------------------------------------------------------------------------
// Launch sequence
// ---------------------------------------------------------------------------
extern "C" void kernel_launch(void* const* d_in, const int* in_sizes, int n_in,
                              void* d_out, int out_size)
{
    const float* hidden = (const float*)d_in[0];   // (SEQ, B, H)
    const float* w_qkv  = (const float*)d_in[1];   // (3H, H)
    const float* w_out  = (const float*)d_in[2];   // (H, H)
    float* out = (float*)d_out;                    // (SEQ, B, H)

    float *qkv, *scores, *ctx;
    cudaGetSymbolAddress((void**)&qkv,    g_qkv);
    cudaGetSymbolAddress((void**)&scores, g_scores);
    cudaGetSymbolAddress((void**)&ctx,    g_ctx);

    const long SH = (long)SEQ * SEQ;   // per-head scores stride

    // 1) QKV projection: g_qkv[4096,6144] = hidden[4096,2048] @ w_qkv^T
    gemm_tile<true><<<dim3(QKVN / 128, MTOT / 128, 1), 256>>>(
        hidden, HID, 0,
        w_qkv,  HID, 0,
        qkv,    QKVN, 0,
        HID, 1.0f);

    // 2) scores[z,s,t] = SCALE * sum_h q[s,h]*k[t,h]
    //    q base offset = z*384, k base = z*384 + 128; row stride = B*QKVN = 12288
    gemm_tile<true><<<dim3(SEQ / 128, SEQ / 128, NHEADS), 256>>>(
        qkv,        BATCH * QKVN, 384,
        qkv + HN,   BATCH * QKVN, 384,
        scores,     SEQ,          SH,
        HN, ATT_SCALE);

    // 3) row softmax over t
    softmax_rows<<<NHEADS * SEQ, 256>>>(scores);

    // 4) ctx: prob[z][s,t] @ v[t,h]; v base = z*384 + 256 (NN GEMM)
    //    C base = g_ctx + z*128, s-row stride = B*HID = 4096
    gemm_tile<false><<<dim3(HN / 128, SEQ / 128, NHEADS), 256>>>(
        scores,          SEQ,          SH,
        qkv + 2 * HN,    BATCH * QKVN, 384,
        ctx,             BATCH * HID,  HN,
        SEQ, 1.0f);

    // 5) output projection: out[4096,2048] = ctx[4096,2048] @ w_out^T
    gemm_tile<true><<<dim3(HID / 128, MTOT / 128, 1), 256>>>(
        ctx,   HID, 0,
        w_out, HID, 0,
        out,   HID, 0,
        HID, 1.0f);
}

// round 3
// speedup vs baseline: 2.3054x; 2.3054x over previous
#include <cuda_runtime.h>
#include <cstdint>

#define SEQ    2048
#define BATCH  2
#define HID    2048
#define NPH    16
#define HN     128
#define MTOT   (SEQ*BATCH)     // 4096
#define QKVN   (3*HID)         // 6144
#define NHEADS (BATCH*NPH)     // 32
#define ATT_SCALE (1.0f/11.313708498984761f)

// Scratch (device globals; no allocation allowed in kernel_launch)
__device__ float g_qkv[(size_t)MTOT * QKVN];
__device__ float g_scores[(size_t)NHEADS * SEQ * SEQ];
__device__ float g_ctx[(size_t)MTOT * HID];

__device__ __forceinline__ uint32_t f2tf32(float x) {
    uint32_t r;
    asm("cvt.rna.tf32.f32 %0, %1;" : "=r"(r) : "f"(x));
    return r;
}

__device__ __forceinline__ void mma_tf32(float* d, const uint32_t* a, const uint32_t* b) {
    asm volatile(
        "mma.sync.aligned.m16n8k8.row.col.f32.tf32.tf32.f32 "
        "{%0,%1,%2,%3}, {%4,%5,%6,%7}, {%8,%9}, {%0,%1,%2,%3};"
        : "+f"(d[0]), "+f"(d[1]), "+f"(d[2]), "+f"(d[3])
        : "r"(a[0]), "r"(a[1]), "r"(a[2]), "r"(a[3]), "r"(b[0]), "r"(b[1]));
}

// ---------------------------------------------------------------------------
// Batched tiled GEMM on tf32 tensor cores.
//   NT=true :  C[m,n] = alpha * sum_k A[m,k] * B[n,k]
//   NT=false:  C[m,n] = alpha * sum_k A[m,k] * B[k,n]
// BM=BN=128, BK=16, 256 threads (8 warps, 2x4), warp tile 64x32.
// M,N multiples of 128; K multiple of 16. z-batch with linear strides.
// ---------------------------------------------------------------------------
#define SPAD 136   // 128 + 8 pad -> conflict-free fragment reads

template <bool NT>
__global__ void __launch_bounds__(256, 2)
gemm_mma(const float* __restrict__ A, int lda, long sAz,
         const float* __restrict__ B, int ldb, long sBz,
         float*       __restrict__ C, int ldc, long sCz,
         int K, float alpha)
{
    __shared__ uint32_t As[2][16][SPAD];  // [k][m]
    __shared__ uint32_t Bs[2][16][SPAD];  // [k][n]

    const int z = blockIdx.z;
    A += (long)z * sAz;
    B += (long)z * sBz;
    C += (long)z * sCz;

    const int m0 = blockIdx.y * 128;
    const int n0 = blockIdx.x * 128;
    const int t    = threadIdx.x;
    const int lane = t & 31;
    const int warp = t >> 5;
    const int wm = (warp >> 2) * 64;   // 2 warps along m
    const int wn = (warp & 3)  * 32;   // 4 warps along n
    const int gid = lane >> 2;         // 0..7
    const int tg  = lane & 3;          // 0..3

    // K-major tile load mapping (A always; B when NT): 128 rows x 16 k-cols.
    const int lr = t >> 1;             // row 0..127
    const int lc = (t & 1) * 8;        // k col 0 or 8 (two float4 each)
    // NN B tile mapping: 16 k-rows x 128 cols, two float4 per thread.
    const int nr0 = (t * 2)     >> 5;  // k row of first float4
    const int nc0 = ((t * 2) & 31) * 4;
    const int nr1 = (t * 2 + 1) >> 5;
    const int nc1 = ((t * 2 + 1) & 31) * 4;

    float acc[4][4][4];
#pragma unroll
    for (int i = 0; i < 4; i++)
#pragma unroll
        for (int j = 0; j < 4; j++)
#pragma unroll
            for (int r = 0; r < 4; r++) acc[i][j][r] = 0.0f;

    const int iters = K / 16;

    // ---- prologue: load tile 0 into stage 0 ----
    {
        float4 a0 = *(const float4*)(A + (long)(m0 + lr) * lda + lc);
        float4 a1 = *(const float4*)(A + (long)(m0 + lr) * lda + lc + 4);
        As[0][lc + 0][lr] = f2tf32(a0.x); As[0][lc + 1][lr] = f2tf32(a0.y);
        As[0][lc + 2][lr] = f2tf32(a0.z); As[0][lc + 3][lr] = f2tf32(a0.w);
        As[0][lc + 4][lr] = f2tf32(a1.x); As[0][lc + 5][lr] = f2tf32(a1.y);
        As[0][lc + 6][lr] = f2tf32(a1.z); As[0][lc + 7][lr] = f2tf32(a1.w);
        if (NT) {
            float4 b0 = *(const float4*)(B + (long)(n0 + lr) * ldb + lc);
            float4 b1 = *(const float4*)(B + (long)(n0 + lr) * ldb + lc + 4);
            Bs[0][lc + 0][lr] = f2tf32(b0.x); Bs[0][lc + 1][lr] = f2tf32(b0.y);
            Bs[0][lc + 2][lr] = f2tf32(b0.z); Bs[0][lc + 3][lr] = f2tf32(b0.w);
            Bs[0][lc + 4][lr] = f2tf32(b1.x); Bs[0][lc + 5][lr] = f2tf32(b1.y);
            Bs[0][lc + 6][lr] = f2tf32(b1.z); Bs[0][lc + 7][lr] = f2tf32(b1.w);
        } else {
            float4 b0 = *(const float4*)(B + (long)nr0 * ldb + n0 + nc0);
            float4 b1 = *(const float4*)(B + (long)nr1 * ldb + n0 + nc1);
            Bs[0][nr0][nc0 + 0] = f2tf32(b0.x); Bs[0][nr0][nc0 + 1] = f2tf32(b0.y);
            Bs[0][nr0][nc0 + 2] = f2tf32(b0.z); Bs[0][nr0][nc0 + 3] = f2tf32(b0.w);
            Bs[0][nr1][nc1 + 0] = f2tf32(b1.x); Bs[0][nr1][nc1 + 1] = f2tf32(b1.y);
            Bs[0][nr1][nc1 + 2] = f2tf32(b1.z); Bs[0][nr1][nc1 + 3] = f2tf32(b1.w);
        }
    }
    __syncthreads();

    int st = 0;
    for (int kt = 0; kt < iters; kt++) {
        const bool has_next = (kt + 1) < iters;
        float4 na0, na1, nb0, nb1;
        if (has_next) {
            const int k0 = (kt + 1) * 16;
            na0 = *(const float4*)(A + (long)(m0 + lr) * lda + k0 + lc);
            na1 = *(const float4*)(A + (long)(m0 + lr) * lda + k0 + lc + 4);
            if (NT) {
                nb0 = *(const float4*)(B + (long)(n0 + lr) * ldb + k0 + lc);
                nb1 = *(const float4*)(B + (long)(n0 + lr) * ldb + k0 + lc + 4);
            } else {
                nb0 = *(const float4*)(B + (long)(k0 + nr0) * ldb + n0 + nc0);
                nb1 = *(const float4*)(B + (long)(k0 + nr1) * ldb + n0 + nc1);
            }
        }

        // ---- compute two k8 slices from stage st ----
#pragma unroll
        for (int s = 0; s < 2; s++) {
            const int k = s * 8;
            uint32_t a[4][4], b[4][2];
#pragma unroll
            for (int mi = 0; mi < 4; mi++) {
                const int row = wm + mi * 16 + gid;
                a[mi][0] = As[st][k + tg    ][row];
                a[mi][1] = As[st][k + tg    ][row + 8];
                a[mi][2] = As[st][k + tg + 4][row];
                a[mi][3] = As[st][k + tg + 4][row + 8];
            }
#pragma unroll
            for (int ni = 0; ni < 4; ni++) {
                const int col = wn + ni * 8 + gid;
                b[ni][0] = Bs[st][k + tg    ][col];
                b[ni][1] = Bs[st][k + tg + 4][col];
            }
#pragma unroll
            for (int mi = 0; mi < 4; mi++)
#pragma unroll
                for (int ni = 0; ni < 4; ni++)
                    mma_tf32(acc[mi][ni], a[mi], b[ni]);
        }

        if (has_next) {
            const int ns = st ^ 1;
            As[ns][lc + 0][lr] = f2tf32(na0.x); As[ns][lc + 1][lr] = f2tf32(na0.y);
            As[ns][lc + 2][lr] = f2tf32(na0.z); As[ns][lc + 3][lr] = f2tf32(na0.w);
            As[ns][lc + 4][lr] = f2tf32(na1.x); As[ns][lc + 5][lr] = f2tf32(na1.y);
            As[ns][lc + 6][lr] = f2tf32(na1.z); As[ns][lc + 7][lr] = f2tf32(na1.w);
            if (NT) {
                Bs[ns][lc + 0][lr] = f2tf32(nb0.x); Bs[ns][lc + 1][lr] = f2tf32(nb0.y);
                Bs[ns][lc + 2][lr] = f2tf32(nb0.z); Bs[ns][lc + 3][lr] = f2tf32(nb0.w);
                Bs[ns][lc + 4][lr] = f2tf32(nb1.x); Bs[ns][lc + 5][lr] = f2tf32(nb1.y);
                Bs[ns][lc + 6][lr] = f2tf32(nb1.z); Bs[ns][lc + 7][lr] = f2tf32(nb1.w);
            } else {
                Bs[ns][nr0][nc0 + 0] = f2tf32(nb0.x); Bs[ns][nr0][nc0 + 1] = f2tf32(nb0.y);
                Bs[ns][nr0][nc0 + 2] = f2tf32(nb0.z); Bs[ns][nr0][nc0 + 3] = f2tf32(nb0.w);
                Bs[ns][nr1][nc1 + 0] = f2tf32(nb1.x); Bs[ns][nr1][nc1 + 1] = f2tf32(nb1.y);
                Bs[ns][nr1][nc1 + 2] = f2tf32(nb1.z); Bs[ns][nr1][nc1 + 3] = f2tf32(nb1.w);
            }
        }
        __syncthreads();
        st ^= 1;
    }

    // ---- epilogue ----
#pragma unroll
    for (int mi = 0; mi < 4; mi++) {
#pragma unroll
        for (int ni = 0; ni < 4; ni++) {
            const int row = m0 + wm + mi * 16 + gid;
            const int col = n0 + wn + ni * 8 + tg * 2;
            float2 v01 = make_float2(acc[mi][ni][0] * alpha, acc[mi][ni][1] * alpha);
            float2 v23 = make_float2(acc[mi][ni][2] * alpha, acc[mi][ni][3] * alpha);
            *(float2*)(C + (long)row * ldc + col)       = v01;
            *(float2*)(C + (long)(row + 8) * ldc + col) = v23;
        }
    }
}

// ---------------------------------------------------------------------------
// Row softmax, in place. One 256-thread block per row of length SEQ.
// ---------------------------------------------------------------------------
__global__ void __launch_bounds__(256)
softmax_rows(float* __restrict__ S)
{
    __shared__ float buf[SEQ];
    __shared__ float red[256];

    const long row = blockIdx.x;
    float* p = S + row * (long)SEQ;
    const int t = threadIdx.x;

    float mx = -3.402823e38f;
    for (int i = t; i < SEQ; i += 256) {
        float v = p[i];
        buf[i] = v;
        mx = fmaxf(mx, v);
    }
    red[t] = mx;
    __syncthreads();
    for (int s = 128; s > 0; s >>= 1) {
        if (t < s) red[t] = fmaxf(red[t], red[t + s]);
        __syncthreads();
    }
    mx = red[0];
    __syncthreads();

    float sum = 0.0f;
    for (int i = t; i < SEQ; i += 256) {
        float e = __expf(buf[i] - mx);
        buf[i] = e;
        sum += e;
    }
    red[t] = sum;
    __syncthreads();
    for (int s = 128; s > 0; s >>= 1) {
        if (t < s) red[t] += red[t + s];
        __syncthreads();
    }
    const float inv = 1.0f / red[0];
    for (int i = t; i < SEQ; i += 256) p[i] = buf[i] * inv;
}

// ---------------------------------------------------------------------------
extern "C" void kernel_launch(void* const* d_in, const int* in_sizes, int n_in,
                              void* d_out, int out_size)
{
    const float* hidden = (const float*)d_in[0];
    const float* w_qkv  = (const float*)d_in[1];
    const float* w_out  = (const float*)d_in[2];
    float* out = (float*)d_out;

    float *qkv, *scores, *ctx;
    cudaGetSymbolAddress((void**)&qkv,    g_qkv);
    cudaGetSymbolAddress((void**)&scores, g_scores);
    cudaGetSymbolAddress((void**)&ctx,    g_ctx);

    const long SH = (long)SEQ * SEQ;

    // 1) QKV projection: [4096,6144] = hidden[4096,2048] @ w_qkv^T
    gemm_mma<true><<<dim3(QKVN / 128, MTOT / 128, 1), 256>>>(
        hidden, HID, 0,  w_qkv, HID, 0,  qkv, QKVN, 0,  HID, 1.0f);

    // 2) scores[z] = SCALE * Q_z K_z^T  (q base z*384, k base z*384+128)
    gemm_mma<true><<<dim3(SEQ / 128, SEQ / 128, NHEADS), 256>>>(
        qkv,      BATCH * QKVN, 384,
        qkv + HN, BATCH * QKVN, 384,
        scores,   SEQ,          SH,
        HN, ATT_SCALE);

    // 3) softmax over last dim
    softmax_rows<<<NHEADS * SEQ, 256>>>(scores);

    // 4) ctx[z] = prob[z] @ V_z  (v base z*384+256), NN
    gemm_mma<false><<<dim3(HN / 128, SEQ / 128, NHEADS), 256>>>(
        scores,       SEQ,          SH,
        qkv + 2 * HN, BATCH * QKVN, 384,
        ctx,          BATCH * HID,  HN,
        SEQ, 1.0f);

    // 5) output projection: out = ctx @ w_out^T
    gemm_mma<true><<<dim3(HID / 128, MTOT / 128, 1), 256>>>(
        ctx, HID, 0,  w_out, HID, 0,  out, HID, 0,  HID, 1.0f);
}

// round 5
// speedup vs baseline: 2.8033x; 1.2160x over previous
#include <cuda_runtime.h>
#include <cstdint>

#define SEQ    2048
#define BATCH  2
#define HID    2048
#define NPH    16
#define HN     128
#define MTOT   (SEQ*BATCH)     // 4096
#define QKVN   (3*HID)         // 6144
#define NHEADS (BATCH*NPH)     // 32
#define ATT_SCALE (1.0f/11.313708498984761f)

// Scratch (device globals; no allocation allowed anywhere)
__device__ float g_qkv[(size_t)MTOT * QKVN];
__device__ float g_scores[(size_t)NHEADS * SEQ * SEQ];
__device__ float g_vT[(size_t)NHEADS * HN * SEQ];
__device__ float g_ctx[(size_t)MTOT * HID];

__device__ __forceinline__ uint32_t f2tf32(float x) {
    uint32_t r; asm("cvt.rna.tf32.f32 %0, %1;" : "=r"(r) : "f"(x)); return r;
}
__device__ __forceinline__ void mma_tf32(float* d, const uint32_t* a, const uint32_t* b) {
    asm volatile(
        "mma.sync.aligned.m16n8k8.row.col.f32.tf32.tf32.f32 "
        "{%0,%1,%2,%3}, {%4,%5,%6,%7}, {%8,%9}, {%0,%1,%2,%3};"
        : "+f"(d[0]), "+f"(d[1]), "+f"(d[2]), "+f"(d[3])
        : "r"(a[0]), "r"(a[1]), "r"(a[2]), "r"(a[3]), "r"(b[0]), "r"(b[1]));
}
__device__ __forceinline__ void ldsm4(uint32_t& r0, uint32_t& r1, uint32_t& r2, uint32_t& r3,
                                      uint32_t addr) {
    asm volatile("ldmatrix.sync.aligned.m8n8.x4.shared.b16 {%0,%1,%2,%3}, [%4];"
                 : "=r"(r0), "=r"(r1), "=r"(r2), "=r"(r3) : "r"(addr));
}

// ---------------------------------------------------------------------------
// Batched tiled GEMM, tf32 mma.sync + ldmatrix fragment loads.
//   NT=true :  C[m,n] = alpha * sum_k A[m,k] * B[n,k]   (both K-major)
//   NT=false:  C[m,n] = alpha * sum_k A[m,k] * B[k,n]
// BM=BN=128, BK=16, 256 threads (8 warps 2x4), warp tile 64x32.
// Smem tiles stored [row][k] with pitch 20 fp32 (80 B) -> ldmatrix
// conflict-free.  M,N % 128 == 0, K % 16 == 0.  z-batched, linear strides.
// ---------------------------------------------------------------------------
#define PITCH 20

template <bool NT>
__global__ void __launch_bounds__(256, 2)
gemm_mma(const float* __restrict__ A, int lda, long sAz,
         const float* __restrict__ B, int ldb, long sBz,
         float*       __restrict__ C, int ldc, long sCz,
         int K, float alpha)
{
    __shared__ uint32_t As[2][128][PITCH];
    __shared__ uint32_t Bs[2][128][PITCH];

    const int z = blockIdx.z;
    A += (long)z * sAz; B += (long)z * sBz; C += (long)z * sCz;

    const int m0 = blockIdx.y * 128;
    const int n0 = blockIdx.x * 128;
    const int t    = threadIdx.x;
    const int lane = t & 31;
    const int warp = t >> 5;
    const int wm = (warp >> 2) * 64;
    const int wn = (warp & 3)  * 32;
    const int gid = lane >> 2;
    const int tg  = lane & 3;

    // ldmatrix lane addressing components
    const int sub = lane >> 3;          // which 8x8 matrix this octet feeds
    const int lr  = lane & 7;           // row within the matrix

    // gmem->smem mapping: row = base + t/4 (+64 on 2nd iter), col quarter = (t&3)*4
    const int lrow = t >> 2;            // 0..63
    const int lcol = (t & 3) * 4;

    // For NT=false, B is [K,N]: load 16 k-rows x 128 n-cols, then store
    // transposed into Bs[n][k] so fragment loading is identical.
    const int nbr = t >> 5;             // k-row 0..7 (+8 on 2nd iter)
    const int nbc = (lane) * 4;         // n col 0..124

    float acc[4][4][4];
#pragma unroll
    for (int i = 0; i < 4; i++)
#pragma unroll
        for (int j = 0; j < 4; j++)
#pragma unroll
            for (int r = 0; r < 4; r++) acc[i][j][r] = 0.0f;

    auto store_a = [&](int st, int it, float4 v) {
        uint4 w = make_uint4(f2tf32(v.x), f2tf32(v.y), f2tf32(v.z), f2tf32(v.w));
        *(uint4*)&As[st][it * 64 + lrow][lcol] = w;
    };
    auto store_b_nt = [&](int st, int it, float4 v) {
        uint4 w = make_uint4(f2tf32(v.x), f2tf32(v.y), f2tf32(v.z), f2tf32(v.w));
        *(uint4*)&Bs[st][it * 64 + lrow][lcol] = w;
    };
    auto store_b_nn = [&](int st, int it, float4 v) {
        const int kr = it * 8 + nbr;
        Bs[st][nbc + 0][kr] = f2tf32(v.x);
        Bs[st][nbc + 1][kr] = f2tf32(v.y);
        Bs[st][nbc + 2][kr] = f2tf32(v.z);
        Bs[st][nbc + 3][kr] = f2tf32(v.w);
    };

    auto load_a_gmem = [&](int k0, int it) {
        return *(const float4*)(A + (long)(m0 + it * 64 + lrow) * lda + k0 + lcol);
    };
    auto load_b_gmem = [&](int k0, int it) {
        if (NT) return *(const float4*)(B + (long)(n0 + it * 64 + lrow) * ldb + k0 + lcol);
        else    return *(const float4*)(B + (long)(k0 + it * 8 + nbr) * ldb + n0 + nbc);
    };

    const uint32_t sbA = (uint32_t)__cvta_generic_to_shared(&As[0][0][0]);
    const uint32_t sbB = (uint32_t)__cvta_generic_to_shared(&Bs[0][0][0]);
    const uint32_t stageBytes = 128 * PITCH * 4;

    // a-frag address: row = wm + mb*16 + lr + (sub&1)*8, col = ks + (sub>>1)*4
    const uint32_t aRowOff = (uint32_t)(wm + lr + (sub & 1) * 8);
    const uint32_t aColOff = (uint32_t)((sub >> 1) * 4);
    // b-frag address: row = wn + (ntp*2 + (sub>>1))*8 + lr, col = ks + (sub&1)*4
    const uint32_t bRowOff = (uint32_t)(wn + (sub >> 1) * 8 + lr);
    const uint32_t bColOff = (uint32_t)((sub & 1) * 4);

    // ---- prologue: tile 0 -> stage 0 ----
    {
        store_a(0, 0, load_a_gmem(0, 0));
        store_a(0, 1, load_a_gmem(0, 1));
        store_b_nt; // silence unused in template branches
        if (NT) { store_b_nt(0, 0, load_b_gmem(0, 0)); store_b_nt(0, 1, load_b_gmem(0, 1)); }
        else    { store_b_nn(0, 0, load_b_gmem(0, 0)); store_b_nn(0, 1, load_b_gmem(0, 1)); }
    }
    __syncthreads();

    const int KT = K / 16;
    int st = 0;
    for (int kt = 0; kt < KT; kt++) {
        const bool has_next = (kt + 1) < KT;
        float4 pa0, pa1, pb0, pb1;
        if (has_next) {
            const int k0 = (kt + 1) * 16;
            pa0 = load_a_gmem(k0, 0);
            pa1 = load_a_gmem(k0, 1);
            pb0 = load_b_gmem(k0, 0);
            pb1 = load_b_gmem(k0, 1);
        }

#pragma unroll
        for (int s = 0; s < 2; s++) {
            const int ks = s * 8;
            uint32_t a[4][4], b[4][2];
#pragma unroll
            for (int mb = 0; mb < 4; mb++) {
                const uint32_t addr = sbA + st * stageBytes
                    + ((aRowOff + mb * 16) * PITCH + ks + aColOff) * 4;
                ldsm4(a[mb][0], a[mb][1], a[mb][2], a[mb][3], addr);
            }
#pragma unroll
            for (int ntp = 0; ntp < 2; ntp++) {
                const uint32_t addr = sbB + st * stageBytes
                    + ((bRowOff + ntp * 16) * PITCH + ks + bColOff) * 4;
                ldsm4(b[ntp * 2][0], b[ntp * 2][1], b[ntp * 2 + 1][0], b[ntp * 2 + 1][1], addr);
            }
#pragma unroll
            for (int mi = 0; mi < 4; mi++)
#pragma unroll
                for (int ni = 0; ni < 4; ni++)
                    mma_tf32(acc[mi][ni], a[mi], b[ni]);
        }

        if (has_next) {
            const int ns = st ^ 1;
            store_a(ns, 0, pa0);
            store_a(ns, 1, pa1);
            if (NT) { store_b_nt(ns, 0, pb0); store_b_nt(ns, 1, pb1); }
            else    { store_b_nn(ns, 0, pb0); store_b_nn(ns, 1, pb1); }
        }
        __syncthreads();
        st ^= 1;
    }

    // ---- epilogue ----
#pragma unroll
    for (int mi = 0; mi < 4; mi++) {
#pragma unroll
        for (int ni = 0; ni < 4; ni++) {
            const int row = m0 + wm + mi * 16 + gid;
            const int col = n0 + wn + ni * 8 + tg * 2;
            float2 v01 = make_float2(acc[mi][ni][0] * alpha, acc[mi][ni][1] * alpha);
            float2 v23 = make_float2(acc[mi][ni][2] * alpha, acc[mi][ni][3] * alpha);
            *(float2*)(C + (long)row * ldc + col)       = v01;
            *(float2*)(C + (long)(row + 8) * ldc + col) = v23;
        }
    }
}

// ---------------------------------------------------------------------------
// Row softmax, in place. One 256-thread block per row of length SEQ.
// ---------------------------------------------------------------------------
__global__ void __launch_bounds__(256)
softmax_rows(float* __restrict__ S)
{
    __shared__ float buf[SEQ];
    __shared__ float red[256];

    const long row = blockIdx.x;
    float* p = S + row * (long)SEQ;
    const int t = threadIdx.x;

    float mx = -3.402823e38f;
    for (int i = t; i < SEQ; i += 256) {
        float v = p[i];
        buf[i] = v;
        mx = fmaxf(mx, v);
    }
    red[t] = mx;
    __syncthreads();
    for (int s = 128; s > 0; s >>= 1) {
        if (t < s) red[t] = fmaxf(red[t], red[t + s]);
        __syncthreads();
    }
    mx = red[0];
    __syncthreads();

    float sum = 0.0f;
    for (int i = t; i < SEQ; i += 256) {
        float e = __expf(buf[i] - mx);
        buf[i] = e;
        sum += e;
    }
    red[t] = sum;
    __syncthreads();
    for (int s = 128; s > 0; s >>= 1) {
        if (t < s) red[t] += red[t + s];
        __syncthreads();
    }
    const float inv = 1.0f / red[0];
    for (int i = t; i < SEQ; i += 256) p[i] = buf[i] * inv;
}

// ---------------------------------------------------------------------------
extern "C" void kernel_launch(void* const* d_in, const int* in_sizes, int n_in,
                              void* d_out, int out_size)
{
    const float* hidden = (const float*)d_in[0];
    const float* w_qkv  = (const float*)d_in[1];
    const float* w_out  = (const float*)d_in[2];
    float* out = (float*)d_out;

    float *qkv, *scores, *ctx;
    cudaGetSymbolAddress((void**)&qkv,    g_qkv);
    cudaGetSymbolAddress((void**)&scores, g_scores);
    cudaGetSymbolAddress((void**)&ctx,    g_ctx);

    const long SH = (long)SEQ * SEQ;

    // 1) QKV projection: [4096,6144] = hidden[4096,2048] @ w_qkv^T
    gemm_mma<true><<<dim3(QKVN / 128, MTOT / 128, 1), 256>>>(
        hidden, HID, 0,  w_qkv, HID, 0,  qkv, QKVN, 0,  HID, 1.0f);

    // 2) scores[z] = SCALE * Q_z K_z^T  (q base z*384, k base z*384+128)
    gemm_mma<true><<<dim3(SEQ / 128, SEQ / 128, NHEADS), 256>>>(
        qkv,      BATCH * QKVN, 384,
        qkv + HN, BATCH * QKVN, 384,
        scores,   SEQ,          SH,
        HN, ATT_SCALE);

    // 3) softmax over last dim
    softmax_rows<<<NHEADS * SEQ, 256>>>(scores);

    // 4) ctx[z] = prob[z] @ V_z  (v base z*384+256), NN — B transposed on store
    gemm_mma<false><<<dim3(HN / 128, SEQ / 128, NHEADS), 256>>>(
        scores,       SEQ,          SH,
        qkv + 2 * HN, BATCH * QKVN, 384,
        ctx,          BATCH * HID,  HN,
        SEQ, 1.0f);

    // 5) output projection: out = ctx @ w_out^T
    gemm_mma<true><<<dim3(HID / 128, MTOT / 128, 1), 256>>>(
        ctx, HID, 0,  w_out, HID, 0,  out, HID, 0,  HID, 1.0f);
}

// round 7
// speedup vs baseline: 3.6696x; 1.3091x over previous
#include <cuda_runtime.h>
#include <cstdint>

#define SEQ    2048
#define BATCH  2
#define HID    2048
#define NPH    16
#define HN     128
#define MTOT   (SEQ*BATCH)     // 4096
#define QKVN   (3*HID)         // 6144
#define NHEADS (BATCH*NPH)     // 32
#define ATT_SCALE (1.0f/11.313708498984761f)

// Scratch (device globals; no allocation allowed anywhere)
__device__ float g_qkv[(size_t)MTOT * QKVN];
__device__ float g_scores[(size_t)NHEADS * SEQ * SEQ];
__device__ float g_vT[(size_t)NHEADS * HN * SEQ];
__device__ float g_ctx[(size_t)MTOT * HID];
__device__ float g_hid[(size_t)MTOT * HID];
__device__ float g_wqkv[(size_t)QKVN * HID];
__device__ float g_wout[(size_t)HID * HID];

__device__ __forceinline__ uint32_t f2tf32(float x) {
    uint32_t r; asm("cvt.rna.tf32.f32 %0, %1;" : "=r"(r) : "f"(x)); return r;
}
__device__ __forceinline__ float f2tf32f(float x) {
    return __uint_as_float(f2tf32(x));
}
__device__ __forceinline__ void mma_tf32(float* d, const uint32_t* a, const uint32_t* b) {
    asm volatile(
        "mma.sync.aligned.m16n8k8.row.col.f32.tf32.tf32.f32 "
        "{%0,%1,%2,%3}, {%4,%5,%6,%7}, {%8,%9}, {%0,%1,%2,%3};"
        : "+f"(d[0]), "+f"(d[1]), "+f"(d[2]), "+f"(d[3])
        : "r"(a[0]), "r"(a[1]), "r"(a[2]), "r"(a[3]), "r"(b[0]), "r"(b[1]));
}
__device__ __forceinline__ void ldsm4(uint32_t& r0, uint32_t& r1, uint32_t& r2, uint32_t& r3,
                                      uint32_t addr) {
    asm volatile("ldmatrix.sync.aligned.m8n8.x4.shared.b16 {%0,%1,%2,%3}, [%4];"
                 : "=r"(r0), "=r"(r1), "=r"(r2), "=r"(r3) : "r"(addr));
}
__device__ __forceinline__ void cp16(uint32_t dst, const void* src) {
    asm volatile("cp.async.cg.shared.global [%0], [%1], 16;" :: "r"(dst), "l"(src));
}

// ---------------------------------------------------------------------------
// NT GEMM: C[m,n] = alpha * sum_k A[m,k] * B[n,k]   (both K-major, pre-rounded
// to tf32 values stored as fp32).  BM=BN=128, BK=16, 256 threads (8 warps 2x4),
// warp tile 64x32.  4-stage cp.async ring; smem pitch 20 fp32 (ldmatrix
// conflict-free).  M,N % 128 == 0, K % 16 == 0, K/16 >= 4.  z-batched.
// If ROUND, output values are rounded to tf32 (they feed another GEMM).
// ---------------------------------------------------------------------------
#define PITCH 20
#define STAGE_BYTES (128 * PITCH * 4)     // 10240 B per array per stage
#define GEMM_SMEM   (8 * STAGE_BYTES)     // 4 stages x (A,B) = 81920 B

template <bool ROUND>
__global__ void __launch_bounds__(256, 2)
gemm_nt(const float* __restrict__ A, int lda, long sAz,
        const float* __restrict__ B, int ldb, long sBz,
        float*       __restrict__ C, int ldc, long sCz,
        int K, float alpha)
{
    extern __shared__ __align__(16) char smem[];
    const uint32_t sb = (uint32_t)__cvta_generic_to_shared(smem);

    const int z = blockIdx.z;
    A += (long)z * sAz; B += (long)z * sBz; C += (long)z * sCz;

    const int m0 = blockIdx.y * 128;
    const int n0 = blockIdx.x * 128;
    const int t    = threadIdx.x;
    const int lane = t & 31;
    const int warp = t >> 5;
    const int wm = (warp >> 2) * 64;
    const int wn = (warp & 3)  * 32;
    const int gid = lane >> 2;
    const int tg  = lane & 3;
    const int sub = lane >> 3;
    const int lr  = lane & 7;

    const int lrow = t >> 2;            // 0..63
    const int lcol = (t & 3) * 4;       // 0,4,8,12

    float acc[4][4][4];
#pragma unroll
    for (int i = 0; i < 4; i++)
#pragma unroll
        for (int j = 0; j < 4; j++)
#pragma unroll
            for (int r = 0; r < 4; r++) acc[i][j][r] = 0.0f;

    auto issue = [&](int kt) {
        const int st = kt & 3;
        const int k0 = kt * 16;
        const uint32_t ab = sb + st * STAGE_BYTES;
        const uint32_t bb = sb + 4 * STAGE_BYTES + st * STAGE_BYTES;
        cp16(ab + ((lrow)      * PITCH + lcol) * 4, A + (long)(m0 + lrow)      * lda + k0 + lcol);
        cp16(ab + ((lrow + 64) * PITCH + lcol) * 4, A + (long)(m0 + lrow + 64) * lda + k0 + lcol);
        cp16(bb + ((lrow)      * PITCH + lcol) * 4, B + (long)(n0 + lrow)      * ldb + k0 + lcol);
        cp16(bb + ((lrow + 64) * PITCH + lcol) * 4, B + (long)(n0 + lrow + 64) * ldb + k0 + lcol);
        asm volatile("cp.async.commit_group;" ::: "memory");
    };

    // fragment addresses (pitch-20 rotation -> conflict-free ldmatrix)
    const uint32_t aRowOff = (uint32_t)(wm + lr + (sub & 1) * 8);
    const uint32_t aColOff = (uint32_t)((sub >> 1) * 4);
    const uint32_t bRowOff = (uint32_t)(wn + (sub >> 1) * 8 + lr);
    const uint32_t bColOff = (uint32_t)((sub & 1) * 4);

    const int KT = K / 16;

    issue(0); issue(1); issue(2);

    for (int kt = 0; kt < KT; kt++) {
        asm volatile("cp.async.wait_group 2;" ::: "memory");
        __syncthreads();
        if (kt + 3 < KT) issue(kt + 3);
        else asm volatile("cp.async.commit_group;" ::: "memory");  // keep count invariant

        const int st = kt & 3;
        const uint32_t aSt = sb + st * STAGE_BYTES;
        const uint32_t bSt = sb + 4 * STAGE_BYTES + st * STAGE_BYTES;
#pragma unroll
        for (int s = 0; s < 2; s++) {
            const int ks = s * 8;
            uint32_t a[4][4], b[4][2];
#pragma unroll
            for (int mb = 0; mb < 4; mb++) {
                const uint32_t addr = aSt + ((aRowOff + mb * 16) * PITCH + ks + aColOff) * 4;
                ldsm4(a[mb][0], a[mb][1], a[mb][2], a[mb][3], addr);
            }
#pragma unroll
            for (int np = 0; np < 2; np++) {
                const uint32_t addr = bSt + ((bRowOff + np * 16) * PITCH + ks + bColOff) * 4;
                ldsm4(b[np * 2][0], b[np * 2][1], b[np * 2 + 1][0], b[np * 2 + 1][1], addr);
            }
#pragma unroll
            for (int mi = 0; mi < 4; mi++)
#pragma unroll
                for (int ni = 0; ni < 4; ni++)
                    mma_tf32(acc[mi][ni], a[mi], b[ni]);
        }
    }

    // ---- epilogue ----
#pragma unroll
    for (int mi = 0; mi < 4; mi++) {
#pragma unroll
        for (int ni = 0; ni < 4; ni++) {
            const int row = m0 + wm + mi * 16 + gid;
            const int col = n0 + wn + ni * 8 + tg * 2;
            float v0 = acc[mi][ni][0] * alpha, v1 = acc[mi][ni][1] * alpha;
            float v2 = acc[mi][ni][2] * alpha, v3 = acc[mi][ni][3] * alpha;
            if (ROUND) { v0 = f2tf32f(v0); v1 = f2tf32f(v1); v2 = f2tf32f(v2); v3 = f2tf32f(v3); }
            *(float2*)(C + (long)row * ldc + col)       = make_float2(v0, v1);
            *(float2*)(C + (long)(row + 8) * ldc + col) = make_float2(v2, v3);
        }
    }
}

// ---------------------------------------------------------------------------
// Elementwise tf32 rounding (for raw inputs)
// ---------------------------------------------------------------------------
__global__ void __launch_bounds__(256)
cvt_tf32(const float* __restrict__ in, float* __restrict__ out, int n4)
{
    const int i = blockIdx.x * 256 + threadIdx.x;
    if (i < n4) {
        float4 v = ((const float4*)in)[i];
        v.x = f2tf32f(v.x); v.y = f2tf32f(v.y);
        v.z = f2tf32f(v.z); v.w = f2tf32f(v.w);
        ((float4*)out)[i] = v;
    }
}

// ---------------------------------------------------------------------------
// V transpose: vT[z][h][t] = qkv[t*12288 + z*384 + 256 + h]   (already rounded)
// ---------------------------------------------------------------------------
__global__ void __launch_bounds__(256)
transpose_v(const float* __restrict__ qkv, float* __restrict__ vT)
{
    __shared__ float tile[32][33];
    const int z  = blockIdx.z;
    const int t0 = blockIdx.x * 32;
    const int h0 = blockIdx.y * 32;
    const int x = threadIdx.x, y = threadIdx.y;   // 32 x 8
#pragma unroll
    for (int i = y; i < 32; i += 8)
        tile[i][x] = qkv[(long)(t0 + i) * (BATCH * QKVN) + z * 384 + 2 * HN + h0 + x];
    __syncthreads();
#pragma unroll
    for (int i = y; i < 32; i += 8)
        vT[((long)z * HN + h0 + i) * SEQ + t0 + x] = tile[x][i];
}

// ---------------------------------------------------------------------------
// Row softmax, in place, register-resident (8 floats/thread), rounds output
// to tf32 (it feeds the PV GEMM A operand).
// ---------------------------------------------------------------------------
__global__ void __launch_bounds__(256)
softmax_rows(float* __restrict__ S)
{
    __shared__ float red[8];
    const long row = blockIdx.x;
    float4* p = (float4*)(S + row * (long)SEQ);
    const int t = threadIdx.x;
    const int lane = t & 31, warp = t >> 5;

    float4 v0 = p[t], v1 = p[t + 256];
    float mx = fmaxf(fmaxf(fmaxf(v0.x, v0.y), fmaxf(v0.z, v0.w)),
                     fmaxf(fmaxf(v1.x, v1.y), fmaxf(v1.z, v1.w)));
#pragma unroll
    for (int o = 16; o > 0; o >>= 1) mx = fmaxf(mx, __shfl_xor_sync(0xffffffffu, mx, o));
    if (lane == 0) red[warp] = mx;
    __syncthreads();
    mx = red[lane & 7];
#pragma unroll
    for (int o = 4; o > 0; o >>= 1) mx = fmaxf(mx, __shfl_xor_sync(0xffffffffu, mx, o));

    v0.x = __expf(v0.x - mx); v0.y = __expf(v0.y - mx);
    v0.z = __expf(v0.z - mx); v0.w = __expf(v0.w - mx);
    v1.x = __expf(v1.x - mx); v1.y = __expf(v1.y - mx);
    v1.z = __expf(v1.z - mx); v1.w = __expf(v1.w - mx);
    float sum = v0.x + v0.y + v0.z + v0.w + v1.x + v1.y + v1.z + v1.w;
#pragma unroll
    for (int o = 16; o > 0; o >>= 1) sum += __shfl_xor_sync(0xffffffffu, sum, o);
    __syncthreads();
    if (lane == 0) red[warp] = sum;
    __syncthreads();
    sum = red[lane & 7];
#pragma unroll
    for (int o = 4; o > 0; o >>= 1) sum += __shfl_xor_sync(0xffffffffu, sum, o);

    const float inv = 1.0f / sum;
    v0.x = f2tf32f(v0.x * inv); v0.y = f2tf32f(v0.y * inv);
    v0.z = f2tf32f(v0.z * inv); v0.w = f2tf32f(v0.w * inv);
    v1.x = f2tf32f(v1.x * inv); v1.y = f2tf32f(v1.y * inv);
    v1.z = f2tf32f(v1.z * inv); v1.w = f2tf32f(v1.w * inv);
    p[t] = v0; p[t + 256] = v1;
}

// ---------------------------------------------------------------------------
extern "C" void kernel_launch(void* const* d_in, const int* in_sizes, int n_in,
                              void* d_out, int out_size)
{
    const float* hidden = (const float*)d_in[0];
    const float* w_qkv  = (const float*)d_in[1];
    const float* w_out  = (const float*)d_in[2];
    float* out = (float*)d_out;

    float *qkv, *scores, *vT, *ctx, *hidr, *wqkvr, *woutr;
    cudaGetSymbolAddress((void**)&qkv,    g_qkv);
    cudaGetSymbolAddress((void**)&scores, g_scores);
    cudaGetSymbolAddress((void**)&vT,     g_vT);
    cudaGetSymbolAddress((void**)&ctx,    g_ctx);
    cudaGetSymbolAddress((void**)&hidr,   g_hid);
    cudaGetSymbolAddress((void**)&wqkvr,  g_wqkv);
    cudaGetSymbolAddress((void**)&woutr,  g_wout);

    cudaFuncSetAttribute(gemm_nt<true>,  cudaFuncAttributeMaxDynamicSharedMemorySize, GEMM_SMEM);
    cudaFuncSetAttribute(gemm_nt<false>, cudaFuncAttributeMaxDynamicSharedMemorySize, GEMM_SMEM);

    const long SH = (long)SEQ * SEQ;

    // 0) pre-round raw inputs to tf32 values
    cvt_tf32<<<(MTOT * HID / 4 + 255) / 256, 256>>>(hidden, hidr, MTOT * HID / 4);
    cvt_tf32<<<(QKVN * HID / 4 + 255) / 256, 256>>>(w_qkv, wqkvr, QKVN * HID / 4);
    cvt_tf32<<<(HID * HID / 4 + 255) / 256, 256>>>(w_out, woutr, HID * HID / 4);

    // 1) QKV projection (epilogue rounds -> qkv holds tf32 values)
    gemm_nt<true><<<dim3(QKVN / 128, MTOT / 128, 1), 256, GEMM_SMEM>>>(
        hidr, HID, 0,  wqkvr, HID, 0,  qkv, QKVN, 0,  HID, 1.0f);

    // V transpose for PV GEMM
    transpose_v<<<dim3(SEQ / 32, HN / 32, NHEADS), dim3(32, 8)>>>(qkv, vT);

    // 2) scores[z] = SCALE * Q_z K_z^T  (no output rounding — feeds softmax)
    gemm_nt<false><<<dim3(SEQ / 128, SEQ / 128, NHEADS), 256, GEMM_SMEM>>>(
        qkv,      BATCH * QKVN, 384,
        qkv + HN, BATCH * QKVN, 384,
        scores,   SEQ,          SH,
        HN, ATT_SCALE);

    // 3) softmax (store rounds to tf32)
    softmax_rows<<<NHEADS * SEQ, 256>>>(scores);

    // 4) ctx[z] = prob[z] @ vT[z]^T  (epilogue rounds — feeds out-proj)
    gemm_nt<true><<<dim3(HN / 128, SEQ / 128, NHEADS), 256, GEMM_SMEM>>>(
        scores, SEQ,         SH,
        vT,     SEQ,         (long)HN * SEQ,
        ctx,    BATCH * HID, HN,
        SEQ, 1.0f);

    // 5) output projection (no rounding — final result)
    gemm_nt<false><<<dim3(HID / 128, MTOT / 128, 1), 256, GEMM_SMEM>>>(
        ctx, HID, 0,  woutr, HID, 0,  out, HID, 0,  HID, 1.0f);
}

// round 10
// speedup vs baseline: 4.0690x; 1.1088x over previous
#include <cuda_runtime.h>
#include <cstdint>

#define SEQ    2048
#define BATCH  2
#define HID    2048
#define NPH    16
#define HN     128
#define MTOT   (SEQ*BATCH)     // 4096
#define QKVN   (3*HID)         // 6144
#define NHEADS (BATCH*NPH)     // 32
#define ATT_SCALE (1.0f/11.313708498984761f)

// Scratch (device globals; no allocation allowed anywhere)
__device__ float g_qkv[(size_t)MTOT * QKVN];
__device__ float g_scores[(size_t)NHEADS * SEQ * SEQ];
__device__ float g_vT[(size_t)NHEADS * HN * SEQ];
__device__ float g_ctx[(size_t)MTOT * HID];
__device__ float g_hid[(size_t)MTOT * HID];
__device__ float g_wqkv[(size_t)QKVN * HID];
__device__ float g_wout[(size_t)HID * HID];

__device__ __forceinline__ uint32_t f2tf32(float x) {
    uint32_t r; asm("cvt.rna.tf32.f32 %0, %1;" : "=r"(r) : "f"(x)); return r;
}
__device__ __forceinline__ float f2tf32f(float x) {
    return __uint_as_float(f2tf32(x));
}
__device__ __forceinline__ void mma_tf32(float* d, const uint32_t* a, const uint32_t* b) {
    asm volatile(
        "mma.sync.aligned.m16n8k8.row.col.f32.tf32.tf32.f32 "
        "{%0,%1,%2,%3}, {%4,%5,%6,%7}, {%8,%9}, {%0,%1,%2,%3};"
        : "+f"(d[0]), "+f"(d[1]), "+f"(d[2]), "+f"(d[3])
        : "r"(a[0]), "r"(a[1]), "r"(a[2]), "r"(a[3]), "r"(b[0]), "r"(b[1]));
}
__device__ __forceinline__ void ldsm4(uint32_t& r0, uint32_t& r1, uint32_t& r2, uint32_t& r3,
                                      uint32_t addr) {
    asm volatile("ldmatrix.sync.aligned.m8n8.x4.shared.b16 {%0,%1,%2,%3}, [%4];"
                 : "=r"(r0), "=r"(r1), "=r"(r2), "=r"(r3) : "r"(addr));
}
__device__ __forceinline__ void cp16(uint32_t dst, const void* src) {
    asm volatile("cp.async.cg.shared.global [%0], [%1], 16;" :: "r"(dst), "l"(src));
}

// ---------------------------------------------------------------------------
// NT GEMM: C[m,n] = alpha * sum_k A[m,k] * B[n,k]   (both K-major, values
// pre-rounded to tf32).  BM=BN=128, BK=32, 256 threads (8 warps 2x4),
// warp tile 64x32.  3-stage cp.async ring (prefetch distance 2); smem pitch
// 36 fp32 -> ldmatrix conflict-free.  M,N % 128 == 0, K % 32 == 0, K/32 >= 2.
// z-batched with linear strides.  If ROUND, outputs rounded to tf32.
// ---------------------------------------------------------------------------
#define PITCH 36
#define STAGE_BYTES (128 * PITCH * 4)     // 18432 B per array per stage
#define GEMM_SMEM   (6 * STAGE_BYTES)     // 3 stages x (A,B) = 110592 B

template <bool ROUND>
__global__ void __launch_bounds__(256, 2)
gemm_nt(const float* __restrict__ A, int lda, long sAz,
        const float* __restrict__ B, int ldb, long sBz,
        float*       __restrict__ C, int ldc, long sCz,
        int K, float alpha)
{
    extern __shared__ __align__(16) char smem[];
    const uint32_t sb = (uint32_t)__cvta_generic_to_shared(smem);

    const int z = blockIdx.z;
    A += (long)z * sAz; B += (long)z * sBz; C += (long)z * sCz;

    const int m0 = blockIdx.y * 128;
    const int n0 = blockIdx.x * 128;
    const int t    = threadIdx.x;
    const int lane = t & 31;
    const int warp = t >> 5;
    const int wm = (warp >> 2) * 64;
    const int wn = (warp & 3)  * 32;
    const int gid = lane >> 2;
    const int tg  = lane & 3;
    const int sub = lane >> 3;
    const int lr  = lane & 7;

    // gmem->smem: 128 rows x 8 16B-chunks per array; 4 chunks per thread.
    const int crow = t >> 3;            // 0..31 (+32*i)
    const int ccol = (t & 7) * 4;       // 0,4,...,28

    float acc[4][4][4];
#pragma unroll
    for (int i = 0; i < 4; i++)
#pragma unroll
        for (int j = 0; j < 4; j++)
#pragma unroll
            for (int r = 0; r < 4; r++) acc[i][j][r] = 0.0f;

    auto issue = [&](int kt) {
        const int st = kt % 3;
        const int k0 = kt * 32;
        const uint32_t ab = sb + st * STAGE_BYTES;
        const uint32_t bb = sb + 3 * STAGE_BYTES + st * STAGE_BYTES;
#pragma unroll
        for (int i = 0; i < 4; i++) {
            const int r = crow + 32 * i;
            cp16(ab + (r * PITCH + ccol) * 4, A + (long)(m0 + r) * lda + k0 + ccol);
            cp16(bb + (r * PITCH + ccol) * 4, B + (long)(n0 + r) * ldb + k0 + ccol);
        }
        asm volatile("cp.async.commit_group;" ::: "memory");
    };

    // fragment addresses (pitch-36 rotation -> conflict-free ldmatrix)
    const uint32_t aRowOff = (uint32_t)(wm + lr + (sub & 1) * 8);
    const uint32_t aColOff = (uint32_t)((sub >> 1) * 4);
    const uint32_t bRowOff = (uint32_t)(wn + (sub >> 1) * 8 + lr);
    const uint32_t bColOff = (uint32_t)((sub & 1) * 4);

    const int KT = K / 32;

    issue(0); issue(1);

    for (int kt = 0; kt < KT; kt++) {
        asm volatile("cp.async.wait_group 1;" ::: "memory");
        __syncthreads();
        if (kt + 2 < KT) issue(kt + 2);
        else asm volatile("cp.async.commit_group;" ::: "memory");  // keep count invariant

        const int st = kt % 3;
        const uint32_t aSt = sb + st * STAGE_BYTES;
        const uint32_t bSt = sb + 3 * STAGE_BYTES + st * STAGE_BYTES;
#pragma unroll
        for (int s = 0; s < 4; s++) {
            const int ks = s * 8;
            uint32_t a[4][4], b[4][2];
#pragma unroll
            for (int mb = 0; mb < 4; mb++) {
                const uint32_t addr = aSt + ((aRowOff + mb * 16) * PITCH + ks + aColOff) * 4;
                ldsm4(a[mb][0], a[mb][1], a[mb][2], a[mb][3], addr);
            }
#pragma unroll
            for (int np = 0; np < 2; np++) {
                const uint32_t addr = bSt + ((bRowOff + np * 16) * PITCH + ks + bColOff) * 4;
                ldsm4(b[np * 2][0], b[np * 2][1], b[np * 2 + 1][0], b[np * 2 + 1][1], addr);
            }
#pragma unroll
            for (int mi = 0; mi < 4; mi++)
#pragma unroll
                for (int ni = 0; ni < 4; ni++)
                    mma_tf32(acc[mi][ni], a[mi], b[ni]);
        }
    }

    // ---- epilogue ----
#pragma unroll
    for (int mi = 0; mi < 4; mi++) {
#pragma unroll
        for (int ni = 0; ni < 4; ni++) {
            const int row = m0 + wm + mi * 16 + gid;
            const int col = n0 + wn + ni * 8 + tg * 2;
            float v0 = acc[mi][ni][0] * alpha, v1 = acc[mi][ni][1] * alpha;
            float v2 = acc[mi][ni][2] * alpha, v3 = acc[mi][ni][3] * alpha;
            if (ROUND) { v0 = f2tf32f(v0); v1 = f2tf32f(v1); v2 = f2tf32f(v2); v3 = f2tf32f(v3); }
            *(float2*)(C + (long)row * ldc + col)       = make_float2(v0, v1);
            *(float2*)(C + (long)(row + 8) * ldc + col) = make_float2(v2, v3);
        }
    }
}

// ---------------------------------------------------------------------------
// Elementwise tf32 rounding (for raw inputs)
// ---------------------------------------------------------------------------
__global__ void __launch_bounds__(256)
cvt_tf32(const float* __restrict__ in, float* __restrict__ out, int n4)
{
    const int i = blockIdx.x * 256 + threadIdx.x;
    if (i < n4) {
        float4 v = ((const float4*)in)[i];
        v.x = f2tf32f(v.x); v.y = f2tf32f(v.y);
        v.z = f2tf32f(v.z); v.w = f2tf32f(v.w);
        ((float4*)out)[i] = v;
    }
}

// ---------------------------------------------------------------------------
// V transpose: vT[z][h][t] = qkv[t*12288 + z*384 + 256 + h]   (already rounded)
// ---------------------------------------------------------------------------
__global__ void __launch_bounds__(256)
transpose_v(const float* __restrict__ qkv, float* __restrict__ vT)
{
    __shared__ float tile[32][33];
    const int z  = blockIdx.z;
    const int t0 = blockIdx.x * 32;
    const int h0 = blockIdx.y * 32;
    const int x = threadIdx.x, y = threadIdx.y;   // 32 x 8
#pragma unroll
    for (int i = y; i < 32; i += 8)
        tile[i][x] = qkv[(long)(t0 + i) * (BATCH * QKVN) + z * 384 + 2 * HN + h0 + x];
    __syncthreads();
#pragma unroll
    for (int i = y; i < 32; i += 8)
        vT[((long)z * HN + h0 + i) * SEQ + t0 + x] = tile[x][i];
}

// ---------------------------------------------------------------------------
// Row softmax, in place, register-resident (8 floats/thread), rounds output
// to tf32 (it feeds the PV GEMM A operand).
// ---------------------------------------------------------------------------
__global__ void __launch_bounds__(256)
softmax_rows(float* __restrict__ S)
{
    __shared__ float red[8];
    const long row = blockIdx.x;
    float4* p = (float4*)(S + row * (long)SEQ);
    const int t = threadIdx.x;
    const int lane = t & 31, warp = t >> 5;

    float4 v0 = p[t], v1 = p[t + 256];
    float mx = fmaxf(fmaxf(fmaxf(v0.x, v0.y), fmaxf(v0.z, v0.w)),
                     fmaxf(fmaxf(v1.x, v1.y), fmaxf(v1.z, v1.w)));
#pragma unroll
    for (int o = 16; o > 0; o >>= 1) mx = fmaxf(mx, __shfl_xor_sync(0xffffffffu, mx, o));
    if (lane == 0) red[warp] = mx;
    __syncthreads();
    mx = red[lane & 7];
#pragma unroll
    for (int o = 4; o > 0; o >>= 1) mx = fmaxf(mx, __shfl_xor_sync(0xffffffffu, mx, o));

    v0.x = __expf(v0.x - mx); v0.y = __expf(v0.y - mx);
    v0.z = __expf(v0.z - mx); v0.w = __expf(v0.w - mx);
    v1.x = __expf(v1.x - mx); v1.y = __expf(v1.y - mx);
    v1.z = __expf(v1.z - mx); v1.w = __expf(v1.w - mx);
    float sum = v0.x + v0.y + v0.z + v0.w + v1.x + v1.y + v1.z + v1.w;
#pragma unroll
    for (int o = 16; o > 0; o >>= 1) sum += __shfl_xor_sync(0xffffffffu, sum, o);
    __syncthreads();
    if (lane == 0) red[warp] = sum;
    __syncthreads();
    sum = red[lane & 7];
#pragma unroll
    for (int o = 4; o > 0; o >>= 1) sum += __shfl_xor_sync(0xffffffffu, sum, o);

    const float inv = 1.0f / sum;
    v0.x = f2tf32f(v0.x * inv); v0.y = f2tf32f(v0.y * inv);
    v0.z = f2tf32f(v0.z * inv); v0.w = f2tf32f(v0.w * inv);
    v1.x = f2tf32f(v1.x * inv); v1.y = f2tf32f(v1.y * inv);
    v1.z = f2tf32f(v1.z * inv); v1.w = f2tf32f(v1.w * inv);
    p[t] = v0; p[t + 256] = v1;
}

// ---------------------------------------------------------------------------
extern "C" void kernel_launch(void* const* d_in, const int* in_sizes, int n_in,
                              void* d_out, int out_size)
{
    const float* hidden = (const float*)d_in[0];
    const float* w_qkv  = (const float*)d_in[1];
    const float* w_out  = (const float*)d_in[2];
    float* out = (float*)d_out;

    float *qkv, *scores, *vT, *ctx, *hidr, *wqkvr, *woutr;
    cudaGetSymbolAddress((void**)&qkv,    g_qkv);
    cudaGetSymbolAddress((void**)&scores, g_scores);
    cudaGetSymbolAddress((void**)&vT,     g_vT);
    cudaGetSymbolAddress((void**)&ctx,    g_ctx);
    cudaGetSymbolAddress((void**)&hidr,   g_hid);
    cudaGetSymbolAddress((void**)&wqkvr,  g_wqkv);
    cudaGetSymbolAddress((void**)&woutr,  g_wout);

    cudaFuncSetAttribute(gemm_nt<true>,  cudaFuncAttributeMaxDynamicSharedMemorySize, GEMM_SMEM);
    cudaFuncSetAttribute(gemm_nt<false>, cudaFuncAttributeMaxDynamicSharedMemorySize, GEMM_SMEM);

    const long SH = (long)SEQ * SEQ;

    // 0) pre-round raw inputs to tf32 values
    cvt_tf32<<<(MTOT * HID / 4 + 255) / 256, 256>>>(hidden, hidr, MTOT * HID / 4);
    cvt_tf32<<<(QKVN * HID / 4 + 255) / 256, 256>>>(w_qkv, wqkvr, QKVN * HID / 4);
    cvt_tf32<<<(HID * HID / 4 + 255) / 256, 256>>>(w_out, woutr, HID * HID / 4);

    // 1) QKV projection (epilogue rounds -> qkv holds tf32 values)
    gemm_nt<true><<<dim3(QKVN / 128, MTOT / 128, 1), 256, GEMM_SMEM>>>(
        hidr, HID, 0,  wqkvr, HID, 0,  qkv, QKVN, 0,  HID, 1.0f);

    // V transpose for PV GEMM
    transpose_v<<<dim3(SEQ / 32, HN / 32, NHEADS), dim3(32, 8)>>>(qkv, vT);

    // 2) scores[z] = SCALE * Q_z K_z^T  (K=128 -> KT=4; no output rounding)
    gemm_nt<false><<<dim3(SEQ / 128, SEQ / 128, NHEADS), 256, GEMM_SMEM>>>(
        qkv,      BATCH * QKVN, 384,
        qkv + HN, BATCH * QKVN, 384,
        scores,   SEQ,          SH,
        HN, ATT_SCALE);

    // 3) softmax (store rounds to tf32)
    softmax_rows<<<NHEADS * SEQ, 256>>>(scores);

    // 4) ctx[z] = prob[z] @ vT[z]^T  (epilogue rounds — feeds out-proj)
    gemm_nt<true><<<dim3(HN / 128, SEQ / 128, NHEADS), 256, GEMM_SMEM>>>(
        scores, SEQ,         SH,
        vT,     SEQ,         (long)HN * SEQ,
        ctx,    BATCH * HID, HN,
        SEQ, 1.0f);

    // 5) output projection (no rounding — final result)
    gemm_nt<false><<<dim3(HID / 128, MTOT / 128, 1), 256, GEMM_SMEM>>>(
        ctx, HID, 0,  woutr, HID, 0,  out, HID, 0,  HID, 1.0f);
}